// round 8
// baseline (speedup 1.0000x reference)
#include <cuda_runtime.h>
#include <math.h>

#define CHANNELS 192
#define CPARAMS  43

// Table: v range [-6.5, 6.5], step h = 1/64
#define NK      832              // 13 * 64 intervals per channel
#define OFFK    64               // 1.0 / h
#define NC      (NK + OFFK + 3)  // 899 CDF samples per channel
#define H_STEP  (1.0f / 64.0f)
#define INV_H   64.0f
#define V_OFF   416.0f           // 6.5 * 64

#define GRP      8                       // channels per main-kernel block
#define NGRP     (CHANNELS / GRP)        // 24
#define NCHUNK   12                      // 24*12 = 288 blocks ~ 1 wave @ 2 CTA/SM
#define MAIN_THREADS 512
#define ROWS_PER_ITER (MAIN_THREADS / GRP)   // 64
#define UB 8
#define SMEM_BYTES (NK * GRP * 16)       // 106,496 B -> 2 CTAs/SM

// Cubic coefficients, transposed per group: g_coef[(g*NK + i)*GRP + c] (~2.6 MB)
__device__ float4 g_coef[NGRP * NK * GRP];

// ---------------------------------------------------------------------------

__device__ __forceinline__ float softplus_acc(float v) {
    return fmaxf(v, 0.0f) + log1pf(expf(-fabsf(v)));
}
__device__ __forceinline__ float tanh_fast(float x) {
    x = fminf(fmaxf(x, -20.0f), 20.0f);
    float e = __expf(-2.0f * x);
    return __fdividef(1.0f - e, 1.0f + e);
}
__device__ __forceinline__ float sigmoid_fast(float x) {
    return __fdividef(1.0f, 1.0f + __expf(-x));
}

__device__ __forceinline__ float cdf_eval(float u, const float* __restrict__ K) {
    float h[3];
#pragma unroll
    for (int j = 0; j < 3; j++) {
        h[j] = fmaf(u, K[j], K[3 + j]);
        h[j] = fmaf(K[6 + j], tanh_fast(h[j]), h[j]);
    }
    float y[3];
#pragma unroll
    for (int p = 0; p < 3; p++) y[p] = K[18 + p];
#pragma unroll
    for (int i = 0; i < 3; i++)
#pragma unroll
        for (int p = 0; p < 3; p++) y[p] = fmaf(h[i], K[9 + i * 3 + p], y[p]);
#pragma unroll
    for (int j = 0; j < 3; j++) y[j] = fmaf(K[21 + j], tanh_fast(y[j]), y[j]);
    float z[3];
#pragma unroll
    for (int p = 0; p < 3; p++) z[p] = K[33 + p];
#pragma unroll
    for (int i = 0; i < 3; i++)
#pragma unroll
        for (int p = 0; p < 3; p++) z[p] = fmaf(y[i], K[24 + i * 3 + p], z[p]);
#pragma unroll
    for (int j = 0; j < 3; j++) z[j] = fmaf(K[36 + j], tanh_fast(z[j]), z[j]);
    float f = K[42];
#pragma unroll
    for (int i = 0; i < 3; i++) f = fmaf(z[i], K[39 + i], f);
    return sigmoid_fast(f);
}

// Fused prep: one block per channel. Sample all NC CDF values into SMEM,
// emit Catmull-Rom coefficients. grid = CHANNELS, 256 threads.
#define PREP_THREADS 256
__global__ void __launch_bounds__(PREP_THREADS)
de_prep(const float* __restrict__ a0, const float* __restrict__ a1,
        const float* __restrict__ a2,
        const float* __restrict__ b0, const float* __restrict__ b1,
        const float* __restrict__ b2, const float* __restrict__ b3,
        const float* __restrict__ H0, const float* __restrict__ H1,
        const float* __restrict__ H2, const float* __restrict__ H3) {
    __shared__ float sk[CPARAMS];
    __shared__ float W[NC];
    const int c = blockIdx.x;
    const int t = threadIdx.x;

    if (t < CPARAMS) {
        float v;
        if      (t < 3)  v = softplus_acc(H0[c * 3 + t]);
        else if (t < 6)  v = b0[c * 3 + (t - 3)];
        else if (t < 9)  v = tanhf(a0[c * 3 + (t - 6)]);
        else if (t < 18) v = softplus_acc(H1[c * 9 + (t - 9)]);
        else if (t < 21) v = b1[c * 3 + (t - 18)];
        else if (t < 24) v = tanhf(a1[c * 3 + (t - 21)]);
        else if (t < 33) v = softplus_acc(H2[c * 9 + (t - 24)]);
        else if (t < 36) v = b2[c * 3 + (t - 33)];
        else if (t < 39) v = tanhf(a2[c * 3 + (t - 36)]);
        else if (t < 42) v = softplus_acc(H3[c * 3 + (t - 39)]);
        else             v = b3[c];
        sk[t] = v;
    }
    __syncthreads();

    const float u0 = -7.0f - H_STEP;     // cs[j] = cdf(u0 + j*h)
#pragma unroll
    for (int j = t; j < NC; j += PREP_THREADS) {
        float u = fmaf((float)j, H_STEP, u0);
        W[j] = cdf_eval(u, sk);
    }
    __syncthreads();

    const int g  = c >> 3;
    const int cg = c & 7;
    for (int i = t; i < NK; i += PREP_THREADS) {
        float s0 = W[i + 0 + OFFK] - W[i + 0];
        float s1 = W[i + 1 + OFFK] - W[i + 1];
        float s2 = W[i + 2 + OFFK] - W[i + 2];
        float s3 = W[i + 3 + OFFK] - W[i + 3];
        float A = s1;
        float B = 0.5f * (s2 - s0);
        float C = s0 - 2.5f * s1 + 2.0f * s2 - 0.5f * s3;
        float D = 0.5f * (s3 - s0) + 1.5f * (s1 - s2);
        g_coef[(g * NK + i) * GRP + cg] = make_float4(A, B, C, D);
    }
}

// Main: 512 threads, 2 CTAs/SM, 64-reg budget, explicit MLP=8 on LDG and LDS.
// grid = (NCHUNK, NGRP).
__global__ void __launch_bounds__(MAIN_THREADS, 2)
de_main(const float* __restrict__ xin, float* __restrict__ out, int rows) {
    extern __shared__ float4 s_tab[];      // [NK][GRP]
    const int t = threadIdx.x;
    const int g = blockIdx.y;

    const float4* __restrict__ gsrc = g_coef + g * NK * GRP;
    for (int j = t; j < NK * GRP; j += MAIN_THREADS)
        s_tab[j] = __ldg(&gsrc[j]);
    __syncthreads();

    const int c   = t & (GRP - 1);
    const int rl  = t >> 3;                // 0..63
    const int col = g * GRP + c;

    const int chunk  = blockIdx.x;
    const int rbase  = rows / NCHUNK;
    const int rextra = rows - rbase * NCHUNK;
    const int r0     = chunk * rbase + min(chunk, rextra);
    const int nrows  = rbase + (chunk < rextra ? 1 : 0);
    const int r_end  = r0 + nrows;

    int r = r0 + rl;
    const int nfull = nrows / (ROWS_PER_ITER * UB);

    for (int b = 0; b < nfull; b++) {
        // stage 1: 8 streaming loads -> clamped float table coordinate
        float uu[UB];
#pragma unroll
        for (int u = 0; u < UB; u++) {
            float v = __ldcs(&xin[(r + u * ROWS_PER_ITER) * CHANNELS + col]);
            float q = fmaf(v, INV_H, V_OFF);
            uu[u] = fminf(fmaxf(q, 0.0f), (float)NK - 0.001f);
        }
        // stage 2: 8 concurrent LDS.128 gathers
        float4 C[UB];
#pragma unroll
        for (int u = 0; u < UB; u++) {
            int i = (int)uu[u];
            C[u] = s_tab[i * GRP + c];
        }
        // stage 3: Horner + streaming stores
#pragma unroll
        for (int u = 0; u < UB; u++) {
            int i = (int)uu[u];
            float tf = uu[u] - (float)i;
            __stcs(&out[(r + u * ROWS_PER_ITER) * CHANNELS + col],
                   fmaf(tf, fmaf(tf, fmaf(tf, C[u].w, C[u].z), C[u].y), C[u].x));
        }
        r += ROWS_PER_ITER * UB;
    }

    // remainder: UB=4 batches then scalar
    while (r + 3 * ROWS_PER_ITER < r_end) {
        float uu[4];
#pragma unroll
        for (int u = 0; u < 4; u++) {
            float v = __ldcs(&xin[(r + u * ROWS_PER_ITER) * CHANNELS + col]);
            float q = fmaf(v, INV_H, V_OFF);
            uu[u] = fminf(fmaxf(q, 0.0f), (float)NK - 0.001f);
        }
        float4 C[4];
#pragma unroll
        for (int u = 0; u < 4; u++) {
            int i = (int)uu[u];
            C[u] = s_tab[i * GRP + c];
        }
#pragma unroll
        for (int u = 0; u < 4; u++) {
            int i = (int)uu[u];
            float tf = uu[u] - (float)i;
            __stcs(&out[(r + u * ROWS_PER_ITER) * CHANNELS + col],
                   fmaf(tf, fmaf(tf, fmaf(tf, C[u].w, C[u].z), C[u].y), C[u].x));
        }
        r += 4 * ROWS_PER_ITER;
    }
    for (; r < r_end; r += ROWS_PER_ITER) {
        float v = __ldcs(&xin[r * CHANNELS + col]);
        float q = fmaf(v, INV_H, V_OFF);
        float uu = fminf(fmaxf(q, 0.0f), (float)NK - 0.001f);
        int i = (int)uu;
        float tf = uu - (float)i;
        float4 C = s_tab[i * GRP + c];
        __stcs(&out[r * CHANNELS + col],
               fmaf(tf, fmaf(tf, fmaf(tf, C.w, C.z), C.y), C.x));
    }
}

// ---------------------------------------------------------------------------

extern "C" void kernel_launch(void* const* d_in, const int* in_sizes, int n_in,
                              void* d_out, int out_size) {
    const float* x  = (const float*)d_in[0];
    const float* a0 = (const float*)d_in[1];
    const float* a1 = (const float*)d_in[2];
    const float* a2 = (const float*)d_in[3];
    const float* b0 = (const float*)d_in[4];
    const float* b1 = (const float*)d_in[5];
    const float* b2 = (const float*)d_in[6];
    const float* b3 = (const float*)d_in[7];
    const float* H0 = (const float*)d_in[8];
    const float* H1 = (const float*)d_in[9];
    const float* H2 = (const float*)d_in[10];
    const float* H3 = (const float*)d_in[11];
    float* out = (float*)d_out;

    int total = in_sizes[0];
    int rows  = total / CHANNELS;    // 65536

    static int smem_set = 0;
    if (!smem_set) {
        cudaFuncSetAttribute(de_main, cudaFuncAttributeMaxDynamicSharedMemorySize,
                             SMEM_BYTES);
        smem_set = 1;
    }

    de_prep<<<CHANNELS, PREP_THREADS>>>(a0, a1, a2, b0, b1, b2, b3,
                                        H0, H1, H2, H3);
    dim3 mgrid(NCHUNK, NGRP);
    de_main<<<mgrid, MAIN_THREADS, SMEM_BYTES>>>(x, out, rows);
}

// round 9
// speedup vs baseline: 1.6890x; 1.6890x over previous
#include <cuda_runtime.h>
#include <math.h>

#define CHANNELS 192
#define CPARAMS  43

// Table: v range [-6.5, 6.5], step h = 1/64
#define NK      832              // 13 * 64 intervals per channel
#define OFFK    64               // 1.0 / h
#define NC      (NK + 3 + OFFK)  // 899 CDF samples per channel
#define NSLOT   (NK + 3)         // 835 p-value knots per channel (slot = k+1, k=-1..NK+1)
#define H_STEP  (1.0f / 64.0f)
#define INV_H   64.0f
#define V_OFF   416.0f           // 6.5 * 64

#define GRP      32                      // channels per main-kernel block
#define NGRP     (CHANNELS / GRP)        // 6
#define NCHUNK   48                      // 6*48 = 288 blocks ~ 1 wave @ 2 CTA/SM
#define MAIN_THREADS 512
#define ROWS_PER_ITER (MAIN_THREADS / GRP)   // 16
#define UB 8
#define SMEM_BYTES (NSLOT * GRP * 4)     // 106,880 B -> 2 CTAs/SM

// p values at knots, transposed per group: g_ptab[(g*NSLOT + s)*GRP + c] (~0.64 MB)
__device__ float g_ptab[NGRP * NSLOT * GRP];

// ---------------------------------------------------------------------------

__device__ __forceinline__ float softplus_acc(float v) {
    return fmaxf(v, 0.0f) + log1pf(expf(-fabsf(v)));
}
__device__ __forceinline__ float tanh_fast(float x) {
    x = fminf(fmaxf(x, -20.0f), 20.0f);
    float e = __expf(-2.0f * x);
    return __fdividef(1.0f - e, 1.0f + e);
}
__device__ __forceinline__ float sigmoid_fast(float x) {
    return __fdividef(1.0f, 1.0f + __expf(-x));
}

__device__ __forceinline__ float cdf_eval(float u, const float* __restrict__ K) {
    float h[3];
#pragma unroll
    for (int j = 0; j < 3; j++) {
        h[j] = fmaf(u, K[j], K[3 + j]);
        h[j] = fmaf(K[6 + j], tanh_fast(h[j]), h[j]);
    }
    float y[3];
#pragma unroll
    for (int p = 0; p < 3; p++) y[p] = K[18 + p];
#pragma unroll
    for (int i = 0; i < 3; i++)
#pragma unroll
        for (int p = 0; p < 3; p++) y[p] = fmaf(h[i], K[9 + i * 3 + p], y[p]);
#pragma unroll
    for (int j = 0; j < 3; j++) y[j] = fmaf(K[21 + j], tanh_fast(y[j]), y[j]);
    float z[3];
#pragma unroll
    for (int p = 0; p < 3; p++) z[p] = K[33 + p];
#pragma unroll
    for (int i = 0; i < 3; i++)
#pragma unroll
        for (int p = 0; p < 3; p++) z[p] = fmaf(y[i], K[24 + i * 3 + p], z[p]);
#pragma unroll
    for (int j = 0; j < 3; j++) z[j] = fmaf(K[36 + j], tanh_fast(z[j]), z[j]);
    float f = K[42];
#pragma unroll
    for (int i = 0; i < 3; i++) f = fmaf(z[i], K[39 + i], f);
    return sigmoid_fast(f);
}

// Prep: one block per channel. Sample CDF on NC grid points into SMEM,
// difference into p-knot values. grid = CHANNELS, 256 threads.
#define PREP_THREADS 256
__global__ void __launch_bounds__(PREP_THREADS)
de_prep(const float* __restrict__ a0, const float* __restrict__ a1,
        const float* __restrict__ a2,
        const float* __restrict__ b0, const float* __restrict__ b1,
        const float* __restrict__ b2, const float* __restrict__ b3,
        const float* __restrict__ H0, const float* __restrict__ H1,
        const float* __restrict__ H2, const float* __restrict__ H3) {
    __shared__ float sk[CPARAMS];
    __shared__ float W[NC];
    const int c = blockIdx.x;
    const int t = threadIdx.x;

    if (t < CPARAMS) {
        float v;
        if      (t < 3)  v = softplus_acc(H0[c * 3 + t]);
        else if (t < 6)  v = b0[c * 3 + (t - 3)];
        else if (t < 9)  v = tanhf(a0[c * 3 + (t - 6)]);
        else if (t < 18) v = softplus_acc(H1[c * 9 + (t - 9)]);
        else if (t < 21) v = b1[c * 3 + (t - 18)];
        else if (t < 24) v = tanhf(a1[c * 3 + (t - 21)]);
        else if (t < 33) v = softplus_acc(H2[c * 9 + (t - 24)]);
        else if (t < 36) v = b2[c * 3 + (t - 33)];
        else if (t < 39) v = tanhf(a2[c * 3 + (t - 36)]);
        else if (t < 42) v = softplus_acc(H3[c * 3 + (t - 39)]);
        else             v = b3[c];
        sk[t] = v;
    }
    __syncthreads();

    // W[j] = cdf(u0 + j*h), u0 = -7 - h. Knot k: c(vk-0.5)=W[k+1], c(vk+0.5)=W[k+65].
    const float u0 = -7.0f - H_STEP;
#pragma unroll
    for (int j = t; j < NC; j += PREP_THREADS) {
        float u = fmaf((float)j, H_STEP, u0);
        W[j] = cdf_eval(u, sk);
    }
    __syncthreads();

    const int g  = c >> 5;           // group
    const int cg = c & (GRP - 1);    // channel within group
    for (int s = t; s < NSLOT; s += PREP_THREADS) {
        // slot s holds p at knot k = s-1: p = W[s+OFFK] - W[s]
        g_ptab[(g * NSLOT + s) * GRP + cg] = W[s + OFFK] - W[s];
    }
}

// Main: warp = 32 consecutive channels of one row (1-line LDG/STG);
// value table s_tab[slot][32] -> bank = lane, conflict-free LDS.32 gathers;
// Catmull-Rom cubic computed in-registers from 4 knot values.
// grid = (NCHUNK, NGRP), 512 threads, 2 CTAs/SM.
__global__ void __launch_bounds__(MAIN_THREADS, 2)
de_main(const float* __restrict__ xin, float* __restrict__ out, int rows) {
    extern __shared__ float s_tab[];       // [NSLOT][GRP]
    const int t = threadIdx.x;
    const int g = blockIdx.y;

    const float* __restrict__ gsrc = g_ptab + g * NSLOT * GRP;
    for (int j = t; j < NSLOT * GRP; j += MAIN_THREADS)
        s_tab[j] = __ldg(&gsrc[j]);
    __syncthreads();

    const int c   = t & (GRP - 1);         // lane = channel
    const int w   = t >> 5;                // warp = row offset, 0..15
    const int col = g * GRP + c;

    const int chunk  = blockIdx.x;
    const int rbase  = rows / NCHUNK;
    const int rextra = rows - rbase * NCHUNK;
    const int r0     = chunk * rbase + min(chunk, rextra);
    const int nrows  = rbase + (chunk < rextra ? 1 : 0);
    const int r_end  = r0 + nrows;

    int r = r0 + w;
    const int nfull = nrows / (ROWS_PER_ITER * UB);

    for (int b = 0; b < nfull; b++) {
        // stage 1: UB coalesced streaming loads -> clamped table coordinate
        float uu[UB];
#pragma unroll
        for (int u = 0; u < UB; u++) {
            float v = __ldcs(&xin[(r + u * ROWS_PER_ITER) * CHANNELS + col]);
            float q = fmaf(v, INV_H, V_OFF);
            uu[u] = fminf(fmaxf(q, 0.0f), (float)NK - 0.001f);
        }
        // stage 2+3: 4 conflict-free LDS.32 per element, cubic, coalesced store
#pragma unroll
        for (int u = 0; u < UB; u++) {
            int i = (int)uu[u];
            float tf = uu[u] - (float)i;
            int base = i * GRP + c;
            float fm = s_tab[base];
            float f0 = s_tab[base + GRP];
            float f1 = s_tab[base + 2 * GRP];
            float f2 = s_tab[base + 3 * GRP];
            float A = f0;
            float B = 0.5f * (f1 - fm);
            float Cc = fm - 2.5f * f0 + 2.0f * f1 - 0.5f * f2;
            float D = 0.5f * (f2 - fm) + 1.5f * (f0 - f1);
            __stcs(&out[(r + u * ROWS_PER_ITER) * CHANNELS + col],
                   fmaf(tf, fmaf(tf, fmaf(tf, D, Cc), B), A));
        }
        r += ROWS_PER_ITER * UB;
    }

    // remainder: scalar steps of 16 rows
    for (; r < r_end; r += ROWS_PER_ITER) {
        float v = __ldcs(&xin[r * CHANNELS + col]);
        float q = fmaf(v, INV_H, V_OFF);
        float uu = fminf(fmaxf(q, 0.0f), (float)NK - 0.001f);
        int i = (int)uu;
        float tf = uu - (float)i;
        int base = i * GRP + c;
        float fm = s_tab[base];
        float f0 = s_tab[base + GRP];
        float f1 = s_tab[base + 2 * GRP];
        float f2 = s_tab[base + 3 * GRP];
        float A = f0;
        float B = 0.5f * (f1 - fm);
        float Cc = fm - 2.5f * f0 + 2.0f * f1 - 0.5f * f2;
        float D = 0.5f * (f2 - fm) + 1.5f * (f0 - f1);
        __stcs(&out[r * CHANNELS + col],
               fmaf(tf, fmaf(tf, fmaf(tf, D, Cc), B), A));
    }
}

// ---------------------------------------------------------------------------

extern "C" void kernel_launch(void* const* d_in, const int* in_sizes, int n_in,
                              void* d_out, int out_size) {
    const float* x  = (const float*)d_in[0];
    const float* a0 = (const float*)d_in[1];
    const float* a1 = (const float*)d_in[2];
    const float* a2 = (const float*)d_in[3];
    const float* b0 = (const float*)d_in[4];
    const float* b1 = (const float*)d_in[5];
    const float* b2 = (const float*)d_in[6];
    const float* b3 = (const float*)d_in[7];
    const float* H0 = (const float*)d_in[8];
    const float* H1 = (const float*)d_in[9];
    const float* H2 = (const float*)d_in[10];
    const float* H3 = (const float*)d_in[11];
    float* out = (float*)d_out;

    int total = in_sizes[0];
    int rows  = total / CHANNELS;    // 65536

    static int smem_set = 0;
    if (!smem_set) {
        cudaFuncSetAttribute(de_main, cudaFuncAttributeMaxDynamicSharedMemorySize,
                             SMEM_BYTES);
        smem_set = 1;
    }

    de_prep<<<CHANNELS, PREP_THREADS>>>(a0, a1, a2, b0, b1, b2, b3,
                                        H0, H1, H2, H3);
    dim3 mgrid(NCHUNK, NGRP);
    de_main<<<mgrid, MAIN_THREADS, SMEM_BYTES>>>(x, out, rows);
}

// round 10
// speedup vs baseline: 1.7417x; 1.0312x over previous
#include <cuda_runtime.h>
#include <math.h>

#define CHANNELS 192
#define CPARAMS  43

// Table: v range [-6.5, 6.5], step h = 1/64
#define NK      832              // 13 * 64 intervals per channel
#define OFFK    64               // 1.0 / h in knots
#define NSLOT   (NK + 3)         // 835 p-value knots per channel
#define H_STEP  (1.0f / 64.0f)
#define INV_H   64.0f
#define V_OFF   416.0f           // 6.5 * 64

#define GRP      32                      // channels per main-kernel block
#define NGRP     (CHANNELS / GRP)        // 6
#define NCHUNK   48                      // 6*48 = 288 blocks = 2 CTA/SM on 144 SMs
#define MAIN_THREADS 512
#define ROWS_PER_ITER (MAIN_THREADS / GRP)   // 16
#define UB 8
#define SMEM_BYTES (NSLOT * GRP * 4)     // 106,880 B -> 2 CTAs/SM

// prep split
#define PREP_SPLIT 2
#define PREP_SLOTS 418                   // ceil(NSLOT/2)
#define PREP_WLEN  (PREP_SLOTS + OFFK)   // 482
#define PREP_THREADS 256

// p values at knots, transposed per group: g_ptab[(g*NSLOT + s)*GRP + c] (~0.64 MB)
__device__ float g_ptab[NGRP * NSLOT * GRP];

// ---------------------------------------------------------------------------

__device__ __forceinline__ float softplus_acc(float v) {
    return fmaxf(v, 0.0f) + log1pf(expf(-fabsf(v)));
}
__device__ __forceinline__ float tanh_fast(float x) {
    x = fminf(fmaxf(x, -20.0f), 20.0f);
    float e = __expf(-2.0f * x);
    return __fdividef(1.0f - e, 1.0f + e);
}
__device__ __forceinline__ float sigmoid_fast(float x) {
    return __fdividef(1.0f, 1.0f + __expf(-x));
}

__device__ __forceinline__ float cdf_eval(float u, const float* __restrict__ K) {
    float h[3];
#pragma unroll
    for (int j = 0; j < 3; j++) {
        h[j] = fmaf(u, K[j], K[3 + j]);
        h[j] = fmaf(K[6 + j], tanh_fast(h[j]), h[j]);
    }
    float y[3];
#pragma unroll
    for (int p = 0; p < 3; p++) y[p] = K[18 + p];
#pragma unroll
    for (int i = 0; i < 3; i++)
#pragma unroll
        for (int p = 0; p < 3; p++) y[p] = fmaf(h[i], K[9 + i * 3 + p], y[p]);
#pragma unroll
    for (int j = 0; j < 3; j++) y[j] = fmaf(K[21 + j], tanh_fast(y[j]), y[j]);
    float z[3];
#pragma unroll
    for (int p = 0; p < 3; p++) z[p] = K[33 + p];
#pragma unroll
    for (int i = 0; i < 3; i++)
#pragma unroll
        for (int p = 0; p < 3; p++) z[p] = fmaf(y[i], K[24 + i * 3 + p], z[p]);
#pragma unroll
    for (int j = 0; j < 3; j++) z[j] = fmaf(K[36 + j], tanh_fast(z[j]), z[j]);
    float f = K[42];
#pragma unroll
    for (int i = 0; i < 3; i++) f = fmaf(z[i], K[39 + i], f);
    return sigmoid_fast(f);
}

// Prep: grid = (CHANNELS, PREP_SPLIT). Each block samples a CDF window and
// emits its half of the p-knot table.
__global__ void __launch_bounds__(PREP_THREADS)
de_prep(const float* __restrict__ a0, const float* __restrict__ a1,
        const float* __restrict__ a2,
        const float* __restrict__ b0, const float* __restrict__ b1,
        const float* __restrict__ b2, const float* __restrict__ b3,
        const float* __restrict__ H0, const float* __restrict__ H1,
        const float* __restrict__ H2, const float* __restrict__ H3) {
    __shared__ float sk[CPARAMS];
    __shared__ float W[PREP_WLEN];
    const int c = blockIdx.x;
    const int t = threadIdx.x;
    const int slo = blockIdx.y * PREP_SLOTS;
    const int shi = min(NSLOT, slo + PREP_SLOTS);
    const int wlen = (shi - slo) + OFFK;

    if (t < CPARAMS) {
        float v;
        if      (t < 3)  v = softplus_acc(H0[c * 3 + t]);
        else if (t < 6)  v = b0[c * 3 + (t - 3)];
        else if (t < 9)  v = tanhf(a0[c * 3 + (t - 6)]);
        else if (t < 18) v = softplus_acc(H1[c * 9 + (t - 9)]);
        else if (t < 21) v = b1[c * 3 + (t - 18)];
        else if (t < 24) v = tanhf(a1[c * 3 + (t - 21)]);
        else if (t < 33) v = softplus_acc(H2[c * 9 + (t - 24)]);
        else if (t < 36) v = b2[c * 3 + (t - 33)];
        else if (t < 39) v = tanhf(a2[c * 3 + (t - 36)]);
        else if (t < 42) v = softplus_acc(H3[c * 3 + (t - 39)]);
        else             v = b3[c];
        sk[t] = v;
    }
    __syncthreads();

    // global sample j: cdf(u0 + j*h), u0 = -7 - h; this block needs j in
    // [slo, slo+wlen)
    const float u0 = -7.0f - H_STEP;
    for (int j = t; j < wlen; j += PREP_THREADS) {
        float u = fmaf((float)(slo + j), H_STEP, u0);
        W[j] = cdf_eval(u, sk);
    }
    __syncthreads();

    const int g  = c >> 5;
    const int cg = c & (GRP - 1);
    for (int s = slo + t; s < shi; s += PREP_THREADS) {
        g_ptab[(g * NSLOT + s) * GRP + cg] = W[s - slo + OFFK] - W[s - slo];
    }
}

// Main: warp = 32 consecutive channels of one row (1-line LDG/STG);
// bank = lane conflict-free LDS.32 gathers; double-buffered x prefetch.
// grid = (NCHUNK, NGRP), 512 threads, 2 CTAs/SM.
__global__ void __launch_bounds__(MAIN_THREADS, 2)
de_main(const float* __restrict__ xin, float* __restrict__ out, int rows) {
    extern __shared__ float s_tab[];       // [NSLOT][GRP]
    const int t = threadIdx.x;
    const int g = blockIdx.y;

    const float* __restrict__ gsrc = g_ptab + g * NSLOT * GRP;
    for (int j = t; j < NSLOT * GRP; j += MAIN_THREADS)
        s_tab[j] = __ldg(&gsrc[j]);
    __syncthreads();

    const int c   = t & (GRP - 1);         // lane = channel
    const int w   = t >> 5;                // warp = row offset, 0..15
    const int col = g * GRP + c;

    const int chunk  = blockIdx.x;
    const int rbase  = rows / NCHUNK;
    const int rextra = rows - rbase * NCHUNK;
    const int r0     = chunk * rbase + min(chunk, rextra);
    const int nrows  = rbase + (chunk < rextra ? 1 : 0);
    const int r_end  = r0 + nrows;

    int r = r0 + w;
    const int nfull = nrows / (ROWS_PER_ITER * UB);

    // prologue: prefetch iteration 0
    float vbuf[UB];
    if (nfull > 0) {
#pragma unroll
        for (int u = 0; u < UB; u++)
            vbuf[u] = __ldcs(&xin[(r + u * ROWS_PER_ITER) * CHANNELS + col]);
    }

    for (int b = 0; b < nfull; b++) {
        // consume buffered x into table coordinates
        float uu[UB];
#pragma unroll
        for (int u = 0; u < UB; u++) {
            float q = fmaf(vbuf[u], INV_H, V_OFF);
            uu[u] = fminf(fmaxf(q, 0.0f), (float)NK - 0.001f);
        }
        // prefetch next iteration while we compute this one
        const int rn = r + ROWS_PER_ITER * UB;
        if (b + 1 < nfull) {
#pragma unroll
            for (int u = 0; u < UB; u++)
                vbuf[u] = __ldcs(&xin[(rn + u * ROWS_PER_ITER) * CHANNELS + col]);
        }
        // gather 4 knots, Catmull-Rom cubic, coalesced store
#pragma unroll
        for (int u = 0; u < UB; u++) {
            int i = (int)uu[u];
            float tf = uu[u] - (float)i;
            int base = i * GRP + c;
            float fm = s_tab[base];
            float f0 = s_tab[base + GRP];
            float f1 = s_tab[base + 2 * GRP];
            float f2 = s_tab[base + 3 * GRP];
            float A = f0;
            float B = 0.5f * (f1 - fm);
            float Cc = fm - 2.5f * f0 + 2.0f * f1 - 0.5f * f2;
            float D = 0.5f * (f2 - fm) + 1.5f * (f0 - f1);
            __stcs(&out[(r + u * ROWS_PER_ITER) * CHANNELS + col],
                   fmaf(tf, fmaf(tf, fmaf(tf, D, Cc), B), A));
        }
        r = rn;
    }

    // remainder: scalar steps of 16 rows
    for (; r < r_end; r += ROWS_PER_ITER) {
        float v = __ldcs(&xin[r * CHANNELS + col]);
        float q = fmaf(v, INV_H, V_OFF);
        float uu = fminf(fmaxf(q, 0.0f), (float)NK - 0.001f);
        int i = (int)uu;
        float tf = uu - (float)i;
        int base = i * GRP + c;
        float fm = s_tab[base];
        float f0 = s_tab[base + GRP];
        float f1 = s_tab[base + 2 * GRP];
        float f2 = s_tab[base + 3 * GRP];
        float A = f0;
        float B = 0.5f * (f1 - fm);
        float Cc = fm - 2.5f * f0 + 2.0f * f1 - 0.5f * f2;
        float D = 0.5f * (f2 - fm) + 1.5f * (f0 - f1);
        __stcs(&out[r * CHANNELS + col],
               fmaf(tf, fmaf(tf, fmaf(tf, D, Cc), B), A));
    }
}

// ---------------------------------------------------------------------------

extern "C" void kernel_launch(void* const* d_in, const int* in_sizes, int n_in,
                              void* d_out, int out_size) {
    const float* x  = (const float*)d_in[0];
    const float* a0 = (const float*)d_in[1];
    const float* a1 = (const float*)d_in[2];
    const float* a2 = (const float*)d_in[3];
    const float* b0 = (const float*)d_in[4];
    const float* b1 = (const float*)d_in[5];
    const float* b2 = (const float*)d_in[6];
    const float* b3 = (const float*)d_in[7];
    const float* H0 = (const float*)d_in[8];
    const float* H1 = (const float*)d_in[9];
    const float* H2 = (const float*)d_in[10];
    const float* H3 = (const float*)d_in[11];
    float* out = (float*)d_out;

    int total = in_sizes[0];
    int rows  = total / CHANNELS;    // 65536

    static int smem_set = 0;
    if (!smem_set) {
        cudaFuncSetAttribute(de_main, cudaFuncAttributeMaxDynamicSharedMemorySize,
                             SMEM_BYTES);
        smem_set = 1;
    }

    dim3 pgrid(CHANNELS, PREP_SPLIT);
    de_prep<<<pgrid, PREP_THREADS>>>(a0, a1, a2, b0, b1, b2, b3,
                                     H0, H1, H2, H3);
    dim3 mgrid(NCHUNK, NGRP);
    de_main<<<mgrid, MAIN_THREADS, SMEM_BYTES>>>(x, out, rows);
}

// round 12
// speedup vs baseline: 1.9424x; 1.1152x over previous
#include <cuda_runtime.h>
#include <math.h>
#include <stdint.h>

#define CHANNELS 192
#define CPARAMS  43

// Table: v range [-6.5, 6.5], step h = 1/64
#define NK      832              // 13 * 64 intervals per channel
#define OFFK    64               // 1.0 / h in knots
#define NSLOT   (NK + 3)         // 835 p-value knots per channel
#define H_STEP  (1.0f / 64.0f)
#define INV_H   64.0f
#define V_OFF   416.0f           // 6.5 * 64

#define GRP      32                      // channels per main-kernel block
#define NGRP     (CHANNELS / GRP)        // 6
#define NCHUNK   48                      // 6*48 = 288 blocks = 2 CTA/SM
#define MAIN_THREADS 512
#define ROWS_PER_ITER (MAIN_THREADS / GRP)   // 16
#define UB 8
#define SMEM_BYTES (NSLOT * GRP * 4)     // 106,880 B -> 2 CTAs/SM

// prep split
#define PREP_SPLIT 2
#define PREP_SLOTS 418
#define PREP_WLEN  (PREP_SLOTS + OFFK)
#define PREP_THREADS 256

// p values at knots, transposed per group: g_ptab[(g*NSLOT + s)*GRP + c]
__device__ float g_ptab[NGRP * NSLOT * GRP];

// ---------------------------------------------------------------------------

__device__ __forceinline__ float softplus_acc(float v) {
    return fmaxf(v, 0.0f) + log1pf(expf(-fabsf(v)));
}
__device__ __forceinline__ float tanh_fast(float x) {
    x = fminf(fmaxf(x, -20.0f), 20.0f);
    float e = __expf(-2.0f * x);
    return __fdividef(1.0f - e, 1.0f + e);
}
__device__ __forceinline__ float sigmoid_fast(float x) {
    return __fdividef(1.0f, 1.0f + __expf(-x));
}

__device__ __forceinline__ float cdf_eval(float u, const float* __restrict__ K) {
    float h[3];
#pragma unroll
    for (int j = 0; j < 3; j++) {
        h[j] = fmaf(u, K[j], K[3 + j]);
        h[j] = fmaf(K[6 + j], tanh_fast(h[j]), h[j]);
    }
    float y[3];
#pragma unroll
    for (int p = 0; p < 3; p++) y[p] = K[18 + p];
#pragma unroll
    for (int i = 0; i < 3; i++)
#pragma unroll
        for (int p = 0; p < 3; p++) y[p] = fmaf(h[i], K[9 + i * 3 + p], y[p]);
#pragma unroll
    for (int j = 0; j < 3; j++) y[j] = fmaf(K[21 + j], tanh_fast(y[j]), y[j]);
    float z[3];
#pragma unroll
    for (int p = 0; p < 3; p++) z[p] = K[33 + p];
#pragma unroll
    for (int i = 0; i < 3; i++)
#pragma unroll
        for (int p = 0; p < 3; p++) z[p] = fmaf(y[i], K[24 + i * 3 + p], z[p]);
#pragma unroll
    for (int j = 0; j < 3; j++) z[j] = fmaf(K[36 + j], tanh_fast(z[j]), z[j]);
    float f = K[42];
#pragma unroll
    for (int i = 0; i < 3; i++) f = fmaf(z[i], K[39 + i], f);
    return sigmoid_fast(f);
}

// Prep: grid = (CHANNELS, PREP_SPLIT).
__global__ void __launch_bounds__(PREP_THREADS)
de_prep(const float* __restrict__ a0, const float* __restrict__ a1,
        const float* __restrict__ a2,
        const float* __restrict__ b0, const float* __restrict__ b1,
        const float* __restrict__ b2, const float* __restrict__ b3,
        const float* __restrict__ H0, const float* __restrict__ H1,
        const float* __restrict__ H2, const float* __restrict__ H3) {
    __shared__ float sk[CPARAMS];
    __shared__ float W[PREP_WLEN];
    const int c = blockIdx.x;
    const int t = threadIdx.x;
    const int slo = blockIdx.y * PREP_SLOTS;
    const int shi = min(NSLOT, slo + PREP_SLOTS);
    const int wlen = (shi - slo) + OFFK;

    if (t < CPARAMS) {
        float v;
        if      (t < 3)  v = softplus_acc(H0[c * 3 + t]);
        else if (t < 6)  v = b0[c * 3 + (t - 3)];
        else if (t < 9)  v = tanhf(a0[c * 3 + (t - 6)]);
        else if (t < 18) v = softplus_acc(H1[c * 9 + (t - 9)]);
        else if (t < 21) v = b1[c * 3 + (t - 18)];
        else if (t < 24) v = tanhf(a1[c * 3 + (t - 21)]);
        else if (t < 33) v = softplus_acc(H2[c * 9 + (t - 24)]);
        else if (t < 36) v = b2[c * 3 + (t - 33)];
        else if (t < 39) v = tanhf(a2[c * 3 + (t - 36)]);
        else if (t < 42) v = softplus_acc(H3[c * 3 + (t - 39)]);
        else             v = b3[c];
        sk[t] = v;
    }
    __syncthreads();

    const float u0 = -7.0f - H_STEP;
    for (int j = t; j < wlen; j += PREP_THREADS) {
        float u = fmaf((float)(slo + j), H_STEP, u0);
        W[j] = cdf_eval(u, sk);
    }
    __syncthreads();

    const int g  = c >> 5;
    const int cg = c & (GRP - 1);
    for (int s = slo + t; s < shi; s += PREP_THREADS) {
        g_ptab[(g * NSLOT + s) * GRP + cg] = W[s - slo + OFFK] - W[s - slo];
    }
}

// Catmull-Rom from 4 knot values
__device__ __forceinline__ float cr_eval(float fm, float f0, float f1, float f2,
                                         float tf) {
    float A = f0;
    float B = 0.5f * (f1 - fm);
    float Cc = fm - 2.5f * f0 + 2.0f * f1 - 0.5f * f2;
    float D = 0.5f * (f2 - fm) + 1.5f * (f0 - f1);
    return fmaf(tf, fmaf(tf, fmaf(tf, D, Cc), B), A);
}

// Main: warp = 32 consecutive channels of one row; bank = lane LDS gathers.
// Fully staged pipeline: coords -> 32 LDS in flight -> 8 LDG prefetch -> math.
__global__ void __launch_bounds__(MAIN_THREADS, 2)
de_main(const float* __restrict__ xin, float* __restrict__ out, int rows) {
    extern __shared__ float s_tab[];       // [NSLOT][GRP]
    const int t = threadIdx.x;
    const int g = blockIdx.y;

    // cp.async fill (no register round-trip)
    {
        const float4* __restrict__ gsrc4 =
            reinterpret_cast<const float4*>(g_ptab + g * NSLOT * GRP);
        unsigned int sbase = (unsigned int)__cvta_generic_to_shared(s_tab);
        for (int j = t; j < (NSLOT * GRP) / 4; j += MAIN_THREADS) {
            asm volatile("cp.async.cg.shared.global [%0], [%1], 16;\n"
                         :: "r"(sbase + j * 16), "l"(gsrc4 + j) : "memory");
        }
        asm volatile("cp.async.commit_group;\n" ::: "memory");
        asm volatile("cp.async.wait_group 0;\n" ::: "memory");
    }
    __syncthreads();

    const int c   = t & (GRP - 1);         // lane = channel
    const int w   = t >> 5;                // warp = row offset, 0..15
    const int col = g * GRP + c;

    const int chunk  = blockIdx.x;
    const int rbase  = rows / NCHUNK;
    const int rextra = rows - rbase * NCHUNK;
    const int r0     = chunk * rbase + min(chunk, rextra);
    const int nrows  = rbase + (chunk < rextra ? 1 : 0);
    const int r_end  = r0 + nrows;

    int r = r0 + w;
    const int nfull = nrows / (ROWS_PER_ITER * UB);

    float vbuf[UB];
    if (nfull > 0) {
#pragma unroll
        for (int u = 0; u < UB; u++)
            vbuf[u] = __ldcs(&xin[(r + u * ROWS_PER_ITER) * CHANNELS + col]);
    }

    for (int b = 0; b < nfull; b++) {
        // stage 1: coords (vbuf dies here)
        float uu[UB];
#pragma unroll
        for (int u = 0; u < UB; u++) {
            float q = fmaf(vbuf[u], INV_H, V_OFF);
            uu[u] = fminf(fmaxf(q, 0.0f), (float)NK - 0.001f);
        }
        // stage 2: all 32 LDS issued back-to-back (max shared MLP)
        float f[UB][4];
#pragma unroll
        for (int u = 0; u < UB; u++) {
            int base = (int)uu[u] * GRP + c;
            f[u][0] = s_tab[base];
            f[u][1] = s_tab[base + GRP];
            f[u][2] = s_tab[base + 2 * GRP];
            f[u][3] = s_tab[base + 3 * GRP];
        }
        // stage 3: prefetch next x while gathers are in flight
        const int rn = r + ROWS_PER_ITER * UB;
        if (b + 1 < nfull) {
#pragma unroll
            for (int u = 0; u < UB; u++)
                vbuf[u] = __ldcs(&xin[(rn + u * ROWS_PER_ITER) * CHANNELS + col]);
        }
        // stage 4: math + coalesced streaming stores
#pragma unroll
        for (int u = 0; u < UB; u++) {
            float tf = uu[u] - (float)((int)uu[u]);
            __stcs(&out[(r + u * ROWS_PER_ITER) * CHANNELS + col],
                   cr_eval(f[u][0], f[u][1], f[u][2], f[u][3], tf));
        }
        r = rn;
    }

    // remainder: staged UB=4 batches, then scalar
    while (r + 3 * ROWS_PER_ITER < r_end) {
        float uu[4];
#pragma unroll
        for (int u = 0; u < 4; u++) {
            float v = __ldcs(&xin[(r + u * ROWS_PER_ITER) * CHANNELS + col]);
            float q = fmaf(v, INV_H, V_OFF);
            uu[u] = fminf(fmaxf(q, 0.0f), (float)NK - 0.001f);
        }
        float f[4][4];
#pragma unroll
        for (int u = 0; u < 4; u++) {
            int base = (int)uu[u] * GRP + c;
            f[u][0] = s_tab[base];
            f[u][1] = s_tab[base + GRP];
            f[u][2] = s_tab[base + 2 * GRP];
            f[u][3] = s_tab[base + 3 * GRP];
        }
#pragma unroll
        for (int u = 0; u < 4; u++) {
            float tf = uu[u] - (float)((int)uu[u]);
            __stcs(&out[(r + u * ROWS_PER_ITER) * CHANNELS + col],
                   cr_eval(f[u][0], f[u][1], f[u][2], f[u][3], tf));
        }
        r += 4 * ROWS_PER_ITER;
    }
    for (; r < r_end; r += ROWS_PER_ITER) {
        float v = __ldcs(&xin[r * CHANNELS + col]);
        float q = fmaf(v, INV_H, V_OFF);
        float uu = fminf(fmaxf(q, 0.0f), (float)NK - 0.001f);
        int i = (int)uu;
        float tf = uu - (float)i;
        int base = i * GRP + c;
        __stcs(&out[r * CHANNELS + col],
               cr_eval(s_tab[base], s_tab[base + GRP],
                       s_tab[base + 2 * GRP], s_tab[base + 3 * GRP], tf));
    }
}

// ---------------------------------------------------------------------------

extern "C" void kernel_launch(void* const* d_in, const int* in_sizes, int n_in,
                              void* d_out, int out_size) {
    const float* x  = (const float*)d_in[0];
    const float* a0 = (const float*)d_in[1];
    const float* a1 = (const float*)d_in[2];
    const float* a2 = (const float*)d_in[3];
    const float* b0 = (const float*)d_in[4];
    const float* b1 = (const float*)d_in[5];
    const float* b2 = (const float*)d_in[6];
    const float* b3 = (const float*)d_in[7];
    const float* H0 = (const float*)d_in[8];
    const float* H1 = (const float*)d_in[9];
    const float* H2 = (const float*)d_in[10];
    const float* H3 = (const float*)d_in[11];
    float* out = (float*)d_out;

    int total = in_sizes[0];
    int rows  = total / CHANNELS;    // 65536

    static int smem_set = 0;
    if (!smem_set) {
        cudaFuncSetAttribute(de_main, cudaFuncAttributeMaxDynamicSharedMemorySize,
                             SMEM_BYTES);
        smem_set = 1;
    }

    dim3 pgrid(CHANNELS, PREP_SPLIT);
    de_prep<<<pgrid, PREP_THREADS>>>(a0, a1, a2, b0, b1, b2, b3,
                                     H0, H1, H2, H3);
    dim3 mgrid(NCHUNK, NGRP);
    de_main<<<mgrid, MAIN_THREADS, SMEM_BYTES>>>(x, out, rows);
}